// round 9
// baseline (speedup 1.0000x reference)
#include <cuda_runtime.h>
#include <math.h>

// ---------------------------------------------------------------------------
// Mie scattering, table-based v4:
//   1) reduce:      x_mean partials (float4 x8 unrolled, deterministic)
//   2) coeff+table: fused single block (1024 thr): a_n,b_n in double ->
//                   fp32 p,q in SMEM -> I(theta) on 2048-interval grid,
//                   float4-packed entries
//   3) main:        persistent grid, 8 elems (2 float4) per loop iteration,
//                   cubic Lagrange from float4-packed smem table
// ---------------------------------------------------------------------------

#define N_TERMS    50
#define RED_BLOCKS 576
#define RED_THREADS 256
#define TABLE_N    2048                 // intervals over [0, pi]
#define TABLE_PTS  (TABLE_N + 4)        // scalar points 0..2051
#define TABLE_ENTRIES (TABLE_N + 1)     // float4 entries 0..2048
#define MAIN_BLOCKS 888                 // 6 resident blocks x 148 SMs

static __device__ double g_partials[RED_BLOCKS];
static __device__ float4 g_table4[TABLE_ENTRIES];

// ---------------- Stage 1: partial sums of x = pi*d/lambda ------------------
__global__ void mie_reduce_kernel(const float* __restrict__ d, int n) {
    __shared__ double sh[RED_THREADS];
    float a0 = 0.f, a1 = 0.f, a2 = 0.f, a3 = 0.f;
    int n4 = n >> 2;
    const float4* __restrict__ d4 = (const float4*)d;
    int T   = gridDim.x * blockDim.x;
    int gid = blockIdx.x * blockDim.x + threadIdx.x;

    if (n4 == T * 8) {                 // benchmark shape: exactly 8 float4/thread
#pragma unroll
        for (int k = 0; k < 8; k++) {
            float4 v = d4[gid + k * T];
            a0 += __fdiv_rn(__fmul_rn(3.14159274101257324f, v.x), 5.5e-7f);
            a1 += __fdiv_rn(__fmul_rn(3.14159274101257324f, v.y), 5.5e-7f);
            a2 += __fdiv_rn(__fmul_rn(3.14159274101257324f, v.z), 5.5e-7f);
            a3 += __fdiv_rn(__fmul_rn(3.14159274101257324f, v.w), 5.5e-7f);
        }
    } else {
        for (int i = gid; i < n4; i += T) {
            float4 v = d4[i];
            a0 += __fdiv_rn(__fmul_rn(3.14159274101257324f, v.x), 5.5e-7f);
            a1 += __fdiv_rn(__fmul_rn(3.14159274101257324f, v.y), 5.5e-7f);
            a2 += __fdiv_rn(__fmul_rn(3.14159274101257324f, v.z), 5.5e-7f);
            a3 += __fdiv_rn(__fmul_rn(3.14159274101257324f, v.w), 5.5e-7f);
        }
        for (int i = (n4 << 2) + gid; i < n; i += T)
            a0 += __fdiv_rn(__fmul_rn(3.14159274101257324f, d[i]), 5.5e-7f);
    }

    sh[threadIdx.x] = ((double)a0 + (double)a1) + ((double)a2 + (double)a3);
    __syncthreads();
    for (int s = RED_THREADS / 2; s > 0; s >>= 1) {
        if (threadIdx.x < s) sh[threadIdx.x] += sh[threadIdx.x + s];
        __syncthreads();
    }
    if (threadIdx.x == 0) g_partials[blockIdx.x] = sh[0];
}

// ------- Stage 2 (fused): mean + Mie coefficients + I(theta) table ----------
__global__ void __launch_bounds__(1024) mie_coeff_table_kernel(int n_total) {
    __shared__ double sh[64];
    __shared__ double jx[N_TERMS + 1], yx[N_TERMS + 1], jmx[N_TERMS + 1];
    __shared__ double shx, shmx, sinvx, sinvmx;
    __shared__ float4 spq[N_TERMS];     // fp32 (p.re, p.im, q.re, q.im)
    int t = threadIdx.x;

    // ---- deterministic final mean (threads < 64) ----
    if (t < 64) {
        double s = 0.0;
        for (int i = t; i < RED_BLOCKS; i += 64) s += g_partials[i];
        sh[t] = s;
    }
    __syncthreads();
    if (t < 32) { sh[t] += sh[t + 32]; } __syncthreads();
    if (t < 16) { sh[t] += sh[t + 16]; } __syncthreads();
    if (t < 8)  { sh[t] += sh[t + 8]; }  __syncthreads();
    if (t < 4)  { sh[t] += sh[t + 4]; }  __syncthreads();
    if (t < 2)  { sh[t] += sh[t + 2]; }  __syncthreads();

    if (t == 0) {
        double total = sh[0] + sh[1];
        float xmf = (float)(total / (double)n_total);   // fp32 mean like jnp
        float mxf = __fmul_rn(1.31f, xmf);              // fp32 m*x
        double x  = (double)xmf;
        double mx = (double)mxf;
        double invx  = 1.0 / x;          // only 2 serial fp64 divides
        double invmx = 1.0 / mx;
        shx = x; shmx = mx; sinvx = invx; sinvmx = invmx;

        double sx = sin(x),  cx = cos(x);
        double smx = sin(mx), cmx = cos(mx);
        jx[0]  = sx * invx;
        jx[1]  = sx * invx * invx - cx * invx;
        yx[0]  = -cx * invx;
        yx[1]  = -cx * invx * invx - sx * invx;
        jmx[0] = smx * invmx;
        jmx[1] = smx * invmx * invmx - cmx * invmx;
        for (int k = 1; k < N_TERMS; k++) {
            double c  = (2.0 * k + 1.0) * invx;
            double cm = (2.0 * k + 1.0) * invmx;
            jx[k + 1]  = c  * jx[k]  - jx[k - 1];
            yx[k + 1]  = c  * yx[k]  - yx[k - 1];
            jmx[k + 1] = cm * jmx[k] - jmx[k - 1];
        }
    }
    __syncthreads();

    // ---- Mie coefficients (threads < 50) ----
    if (t < N_TERMS) {
        int n = t + 1;
        double dn = (double)n;
        double x = shx, invx = sinvx, invmx = sinvmx;
        double m = (double)1.31f;

        double jn  = jx[n],  jn1 = jx[n - 1];
        double yn  = yx[n],  yn1 = yx[n - 1];
        double jm  = jmx[n], jm1 = jmx[n - 1];

        double dj = jm1 - (dn + 1.0) * invmx * jm;
        double D  = dj / (jm + 1e-10);

        double psi  = x * jn,  psi1 = x * jn1;
        double chi  = x * yn,  chi1 = x * yn1;   // xi = psi + i*chi

        double nx = dn * invx;
        double fa = D / m + nx;
        double fb = m * D + nx;

        double numa = fa * psi - psi1;
        double dar  = numa + 1e-10;
        double dai  = fa * chi - chi1;
        double ia   = 1.0 / (dar * dar + dai * dai);
        double ar   = numa * dar * ia;
        double ai   = -numa * dai * ia;

        double numb = fb * psi - psi1;
        double dbr  = numb + 1e-10;
        double dbi  = fb * chi - chi1;
        double ib   = 1.0 / (dbr * dbr + dbi * dbi);
        double br   = numb * dbr * ib;
        double bi   = -numb * dbi * ib;

        double cc = 0.5 * (2.0 * dn + 1.0) / (dn * (dn + 1.0));
        spq[t] = make_float4((float)(cc * (ar + br)), (float)(cc * (ai + bi)),
                             (float)(cc * (ar - br)), (float)(cc * (ai - bi)));
    }
    __syncthreads();

    // ---- table: fp32 reference recurrence per grid point ----
    for (int i = t; i < TABLE_PTS; i += 1024) {
        const double H = 3.14159265358979323846 / (double)TABLE_N;
        double thd = (double)i * H;
        float c  = (float)cos(thd);
        float st = (float)sin(thd) + 1e-10f;
        float inv_s = 1.0f / st;
        float pi1 = -sqrtf(fmaxf(1.0f - c * c, 0.0f)) * inv_s;

        // n = 1: tau_1 = c (reference's where-branch)
        float4 w = spq[0];
        float u = pi1 + c, v = pi1 - c;
        float Ar = w.x * u, Ai = w.y * u;
        float Br = w.z * v, Bi = w.w * v;

        float qp = pi1;               // pi_{n-1}
        float qc = 3.0f * c * pi1;    // pi_2  (pi_0 = 0)

#pragma unroll
        for (int nn = 2; nn <= N_TERMS; nn++) {
            const float nf   = (float)nn;
            const float np1  = (float)(nn + 1);
            const float invn = 1.0f / (float)nn;   // compile-time constant

            float t1 = c * qc;
            float ta = fmaf(nf, t1, -np1 * qp);    // tau_n
            float uu = qc + ta;
            float vv = qc - ta;

            w = spq[nn - 1];
            Ar = fmaf(w.x, uu, Ar);
            Ai = fmaf(w.y, uu, Ai);
            Br = fmaf(w.z, vv, Br);
            Bi = fmaf(w.w, vv, Bi);

            float qn = fmaf(np1, t1, ta) * invn;   // pi_{n+1}
            qp = qc; qc = qn;
        }

        const float SCALE = (float)(5.5e-7 * 5.5e-7 /
            (4.0 * 3.14159265358979323846 * 3.14159265358979323846));
        float val = (Ar * Ar + Ai * Ai + Br * Br + Bi * Bi) * SCALE;

        // scatter into the 4 float4 entries that reference point i
#pragma unroll
        for (int cidx = 0; cidx < 4; cidx++) {
            int j = i - cidx;
            if (j >= 0 && j < TABLE_ENTRIES)
                ((float*)&g_table4[j])[cidx] = val;
        }
    }
}

// ---------------- Stage 3: cubic Lagrange from float4-packed table ----------
__device__ __forceinline__ float interp4(const float4* __restrict__ T,
                                         float th, float inv_h) {
    float t  = th * inv_h;
    float jf = floorf(t);
    float s  = t - jf;
    int j = (int)jf - 1;
    j = min(max(j, 0), TABLE_N);           // entries 0..TABLE_N

    float4 v = T[j];                        // one LDS.128: taps j..j+3
    float sm1 = s + 1.0f, s1 = s - 1.0f, s2 = s - 2.0f;
    float a = s * s1;
    float b = sm1 * s2;
    float w0 = -0.16666667f * (a * s2);
    float w1 =  0.5f        * (b * s1);
    float w2 = -0.5f        * (b * s);
    float w3 =  0.16666667f * (sm1 * a);
    return fmaf(w0, v.x, fmaf(w1, v.y, fmaf(w2, v.z, w3 * v.w)));
}

__global__ void __launch_bounds__(256) mie_main_kernel(
    const float* __restrict__ theta, float* __restrict__ out, int n)
{
    __shared__ float4 Ts4[TABLE_ENTRIES];   // 32.8 KB
    for (int i = threadIdx.x; i < TABLE_ENTRIES; i += 256)
        Ts4[i] = g_table4[i];               // coalesced LDG.128
    __syncthreads();

    const float INV_H = (float)TABLE_N / 3.14159265358979323846f;
    int n4 = n >> 2;
    int n8 = n >> 3;
    const float4* __restrict__ th4 = (const float4*)theta;
    float4* __restrict__ out4 = (float4*)out;
    int stride = gridDim.x * blockDim.x;

    // 8 elements (2 independent float4) per loop iteration for MLP
    for (int i8 = blockIdx.x * blockDim.x + threadIdx.x; i8 < n8; i8 += stride) {
        float4 va = th4[2 * i8];
        float4 vb = th4[2 * i8 + 1];
        float4 ra, rb;
        ra.x = interp4(Ts4, va.x, INV_H);
        ra.y = interp4(Ts4, va.y, INV_H);
        ra.z = interp4(Ts4, va.z, INV_H);
        ra.w = interp4(Ts4, va.w, INV_H);
        rb.x = interp4(Ts4, vb.x, INV_H);
        rb.y = interp4(Ts4, vb.y, INV_H);
        rb.z = interp4(Ts4, vb.z, INV_H);
        rb.w = interp4(Ts4, vb.w, INV_H);
        out4[2 * i8]     = ra;
        out4[2 * i8 + 1] = rb;
    }

    // leftover float4 (if n4 odd) + scalar remainder, block 0 only
    if (blockIdx.x == 0) {
        if ((n4 & 1) && threadIdx.x == 1) {
            int i4 = n4 - 1;
            float4 v = th4[i4];
            float4 r;
            r.x = interp4(Ts4, v.x, INV_H);
            r.y = interp4(Ts4, v.y, INV_H);
            r.z = interp4(Ts4, v.z, INV_H);
            r.w = interp4(Ts4, v.w, INV_H);
            out4[i4] = r;
        }
        if (threadIdx.x == 0) {
            for (int e = n4 << 2; e < n; e++)
                out[e] = interp4(Ts4, theta[e], INV_H);
        }
    }
}

// ---------------------------------------------------------------------------
extern "C" void kernel_launch(void* const* d_in, const int* in_sizes, int n_in,
                              void* d_out, int out_size) {
    const float* d     = (const float*)d_in[0];
    const float* theta = (const float*)d_in[1];
    float* out = (float*)d_out;
    int n = in_sizes[0];

    mie_reduce_kernel<<<RED_BLOCKS, RED_THREADS>>>(d, n);
    mie_coeff_table_kernel<<<1, 1024>>>(n);
    mie_main_kernel<<<MAIN_BLOCKS, 256>>>(theta, out, n);
}

// round 10
// speedup vs baseline: 1.2324x; 1.2324x over previous
#include <cuda_runtime.h>
#include <math.h>

// ---------------------------------------------------------------------------
// Mie scattering, table-based v5:
//   1) reduce:      grid 2304, exactly 2 float4/thread, 100% occupancy
//   2) coeff+table: fused single block, 256 threads (no reg cap):
//                   a_n,b_n in double -> fp32 p,q in SMEM ->
//                   I(theta) on 2048-interval grid, float4-packed entries
//   3) main:        persistent grid, far-stride float4 pairs (coalesced,
//                   8 independent LDS chains), cubic Lagrange from smem table
// ---------------------------------------------------------------------------

#define N_TERMS    50
#define RED_BLOCKS 2304
#define RED_THREADS 256
#define TABLE_N    2048                 // intervals over [0, pi]
#define TABLE_PTS  (TABLE_N + 4)        // scalar points 0..2051
#define TABLE_ENTRIES (TABLE_N + 1)     // float4 entries 0..2048
#define MAIN_BLOCKS 888                 // 6 resident blocks x 148 SMs

static __device__ double g_partials[RED_BLOCKS];
static __device__ float4 g_table4[TABLE_ENTRIES];

// ---------------- Stage 1: partial sums of x = pi*d/lambda ------------------
__global__ void mie_reduce_kernel(const float* __restrict__ d, int n) {
    __shared__ double sh[RED_THREADS];
    float a0 = 0.f, a1 = 0.f, a2 = 0.f, a3 = 0.f;
    int n4 = n >> 2;
    const float4* __restrict__ d4 = (const float4*)d;
    int T   = gridDim.x * blockDim.x;
    int gid = blockIdx.x * blockDim.x + threadIdx.x;

    if (n4 == T * 2) {                 // benchmark shape: exactly 2 float4/thread
        float4 va = d4[gid];
        float4 vb = d4[gid + T];
        a0 = __fdiv_rn(__fmul_rn(3.14159274101257324f, va.x), 5.5e-7f)
           + __fdiv_rn(__fmul_rn(3.14159274101257324f, vb.x), 5.5e-7f);
        a1 = __fdiv_rn(__fmul_rn(3.14159274101257324f, va.y), 5.5e-7f)
           + __fdiv_rn(__fmul_rn(3.14159274101257324f, vb.y), 5.5e-7f);
        a2 = __fdiv_rn(__fmul_rn(3.14159274101257324f, va.z), 5.5e-7f)
           + __fdiv_rn(__fmul_rn(3.14159274101257324f, vb.z), 5.5e-7f);
        a3 = __fdiv_rn(__fmul_rn(3.14159274101257324f, va.w), 5.5e-7f)
           + __fdiv_rn(__fmul_rn(3.14159274101257324f, vb.w), 5.5e-7f);
    } else {
        for (int i = gid; i < n4; i += T) {
            float4 v = d4[i];
            a0 += __fdiv_rn(__fmul_rn(3.14159274101257324f, v.x), 5.5e-7f);
            a1 += __fdiv_rn(__fmul_rn(3.14159274101257324f, v.y), 5.5e-7f);
            a2 += __fdiv_rn(__fmul_rn(3.14159274101257324f, v.z), 5.5e-7f);
            a3 += __fdiv_rn(__fmul_rn(3.14159274101257324f, v.w), 5.5e-7f);
        }
        for (int i = (n4 << 2) + gid; i < n; i += T)
            a0 += __fdiv_rn(__fmul_rn(3.14159274101257324f, d[i]), 5.5e-7f);
    }

    sh[threadIdx.x] = ((double)a0 + (double)a1) + ((double)a2 + (double)a3);
    __syncthreads();
    for (int s = RED_THREADS / 2; s > 0; s >>= 1) {
        if (threadIdx.x < s) sh[threadIdx.x] += sh[threadIdx.x + s];
        __syncthreads();
    }
    if (threadIdx.x == 0) g_partials[blockIdx.x] = sh[0];
}

// ------- Stage 2 (fused): mean + Mie coefficients + I(theta) table ----------
__global__ void mie_coeff_table_kernel(int n_total) {   // 256 threads, no cap
    __shared__ double sh[256];
    __shared__ double jx[N_TERMS + 1], yx[N_TERMS + 1], jmx[N_TERMS + 1];
    __shared__ double shx, shmx, sinvx, sinvmx;
    __shared__ float4 spq[N_TERMS];     // fp32 (p.re, p.im, q.re, q.im)
    int t = threadIdx.x;

    // ---- deterministic final mean ----
    double s = 0.0;
    for (int i = t; i < RED_BLOCKS; i += 256) s += g_partials[i];
    sh[t] = s;
    __syncthreads();
    for (int w = 128; w > 0; w >>= 1) {
        if (t < w) sh[t] += sh[t + w];
        __syncthreads();
    }

    if (t == 0) {
        float xmf = (float)(sh[0] / (double)n_total);   // fp32 mean like jnp
        float mxf = __fmul_rn(1.31f, xmf);              // fp32 m*x
        double x  = (double)xmf;
        double mx = (double)mxf;
        double invx  = 1.0 / x;          // only 2 serial fp64 divides
        double invmx = 1.0 / mx;
        shx = x; shmx = mx; sinvx = invx; sinvmx = invmx;

        double sx = sin(x),  cx = cos(x);
        double smx = sin(mx), cmx = cos(mx);
        jx[0]  = sx * invx;
        jx[1]  = sx * invx * invx - cx * invx;
        yx[0]  = -cx * invx;
        yx[1]  = -cx * invx * invx - sx * invx;
        jmx[0] = smx * invmx;
        jmx[1] = smx * invmx * invmx - cmx * invmx;
        for (int k = 1; k < N_TERMS; k++) {
            double c  = (2.0 * k + 1.0) * invx;
            double cm = (2.0 * k + 1.0) * invmx;
            jx[k + 1]  = c  * jx[k]  - jx[k - 1];
            yx[k + 1]  = c  * yx[k]  - yx[k - 1];
            jmx[k + 1] = cm * jmx[k] - jmx[k - 1];
        }
    }
    __syncthreads();

    // ---- Mie coefficients (threads < 50) ----
    if (t < N_TERMS) {
        int n = t + 1;
        double dn = (double)n;
        double x = shx, invx = sinvx, invmx = sinvmx;
        double m = (double)1.31f;

        double jn  = jx[n],  jn1 = jx[n - 1];
        double yn  = yx[n],  yn1 = yx[n - 1];
        double jm  = jmx[n], jm1 = jmx[n - 1];

        double dj = jm1 - (dn + 1.0) * invmx * jm;
        double D  = dj / (jm + 1e-10);

        double psi  = x * jn,  psi1 = x * jn1;
        double chi  = x * yn,  chi1 = x * yn1;   // xi = psi + i*chi

        double nx = dn * invx;
        double fa = D / m + nx;
        double fb = m * D + nx;

        double numa = fa * psi - psi1;
        double dar  = numa + 1e-10;
        double dai  = fa * chi - chi1;
        double ia   = 1.0 / (dar * dar + dai * dai);
        double ar   = numa * dar * ia;
        double ai   = -numa * dai * ia;

        double numb = fb * psi - psi1;
        double dbr  = numb + 1e-10;
        double dbi  = fb * chi - chi1;
        double ib   = 1.0 / (dbr * dbr + dbi * dbi);
        double br   = numb * dbr * ib;
        double bi   = -numb * dbi * ib;

        double cc = 0.5 * (2.0 * dn + 1.0) / (dn * (dn + 1.0));
        spq[t] = make_float4((float)(cc * (ar + br)), (float)(cc * (ai + bi)),
                             (float)(cc * (ar - br)), (float)(cc * (ai - bi)));
    }
    __syncthreads();

    // ---- table: fp32 reference recurrence per grid point ----
    for (int i = t; i < TABLE_PTS; i += 256) {
        const double H = 3.14159265358979323846 / (double)TABLE_N;
        double thd = (double)i * H;
        float c  = (float)cos(thd);
        float st = (float)sin(thd) + 1e-10f;
        float inv_s = 1.0f / st;
        float pi1 = -sqrtf(fmaxf(1.0f - c * c, 0.0f)) * inv_s;

        // n = 1: tau_1 = c (reference's where-branch)
        float4 w = spq[0];
        float u = pi1 + c, v = pi1 - c;
        float Ar = w.x * u, Ai = w.y * u;
        float Br = w.z * v, Bi = w.w * v;

        float qp = pi1;               // pi_{n-1}
        float qc = 3.0f * c * pi1;    // pi_2  (pi_0 = 0)

#pragma unroll
        for (int nn = 2; nn <= N_TERMS; nn++) {
            const float nf   = (float)nn;
            const float np1  = (float)(nn + 1);
            const float invn = 1.0f / (float)nn;   // compile-time constant

            float t1 = c * qc;
            float ta = fmaf(nf, t1, -np1 * qp);    // tau_n
            float uu = qc + ta;
            float vv = qc - ta;

            w = spq[nn - 1];
            Ar = fmaf(w.x, uu, Ar);
            Ai = fmaf(w.y, uu, Ai);
            Br = fmaf(w.z, vv, Br);
            Bi = fmaf(w.w, vv, Bi);

            float qn = fmaf(np1, t1, ta) * invn;   // pi_{n+1}
            qp = qc; qc = qn;
        }

        const float SCALE = (float)(5.5e-7 * 5.5e-7 /
            (4.0 * 3.14159265358979323846 * 3.14159265358979323846));
        float val = (Ar * Ar + Ai * Ai + Br * Br + Bi * Bi) * SCALE;

        // scatter into the 4 float4 entries that reference point i
#pragma unroll
        for (int cidx = 0; cidx < 4; cidx++) {
            int j = i - cidx;
            if (j >= 0 && j < TABLE_ENTRIES)
                ((float*)&g_table4[j])[cidx] = val;
        }
    }
}

// ---------------- Stage 3: cubic Lagrange from float4-packed table ----------
__device__ __forceinline__ float interp4(const float4* __restrict__ T,
                                         float th, float inv_h) {
    float t  = th * inv_h;
    float jf = floorf(t);
    float s  = t - jf;
    int j = (int)jf - 1;
    j = min(max(j, 0), TABLE_N);           // entries 0..TABLE_N

    float4 v = T[j];                        // one LDS.128: taps j..j+3
    float sm1 = s + 1.0f, s1 = s - 1.0f, s2 = s - 2.0f;
    float a = s * s1;
    float b = sm1 * s2;
    float w0 = -0.16666667f * (a * s2);
    float w1 =  0.5f        * (b * s1);
    float w2 = -0.5f        * (b * s);
    float w3 =  0.16666667f * (sm1 * a);
    return fmaf(w0, v.x, fmaf(w1, v.y, fmaf(w2, v.z, w3 * v.w)));
}

__global__ void __launch_bounds__(256) mie_main_kernel(
    const float* __restrict__ theta, float* __restrict__ out, int n)
{
    __shared__ float4 Ts4[TABLE_ENTRIES];   // 32.8 KB
    for (int i = threadIdx.x; i < TABLE_ENTRIES; i += 256)
        Ts4[i] = g_table4[i];               // coalesced LDG.128
    __syncthreads();

    const float INV_H = (float)TABLE_N / 3.14159265358979323846f;
    int n4 = n >> 2;
    int half = n4 >> 1;                     // far-stride pair partner offset
    const float4* __restrict__ th4 = (const float4*)theta;
    float4* __restrict__ out4 = (float4*)out;
    int stride = gridDim.x * blockDim.x;

    // 8 elements per iteration: two coalesced float4 loads half apart
    for (int i = blockIdx.x * blockDim.x + threadIdx.x; i < half; i += stride) {
        float4 va = th4[i];
        float4 vb = th4[i + half];
        float4 ra, rb;
        ra.x = interp4(Ts4, va.x, INV_H);
        ra.y = interp4(Ts4, va.y, INV_H);
        ra.z = interp4(Ts4, va.z, INV_H);
        ra.w = interp4(Ts4, va.w, INV_H);
        rb.x = interp4(Ts4, vb.x, INV_H);
        rb.y = interp4(Ts4, vb.y, INV_H);
        rb.z = interp4(Ts4, vb.z, INV_H);
        rb.w = interp4(Ts4, vb.w, INV_H);
        out4[i]        = ra;
        out4[i + half] = rb;
    }

    // leftover float4 (if n4 odd) + scalar remainder, block 0 only
    if (blockIdx.x == 0) {
        if ((n4 & 1) && threadIdx.x == 1) {
            int i4 = n4 - 1;
            float4 v = th4[i4];
            float4 r;
            r.x = interp4(Ts4, v.x, INV_H);
            r.y = interp4(Ts4, v.y, INV_H);
            r.z = interp4(Ts4, v.z, INV_H);
            r.w = interp4(Ts4, v.w, INV_H);
            out4[i4] = r;
        }
        if (threadIdx.x == 0) {
            for (int e = n4 << 2; e < n; e++)
                out[e] = interp4(Ts4, theta[e], INV_H);
        }
    }
}

// ---------------------------------------------------------------------------
extern "C" void kernel_launch(void* const* d_in, const int* in_sizes, int n_in,
                              void* d_out, int out_size) {
    const float* d     = (const float*)d_in[0];
    const float* theta = (const float*)d_in[1];
    float* out = (float*)d_out;
    int n = in_sizes[0];

    mie_reduce_kernel<<<RED_BLOCKS, RED_THREADS>>>(d, n);
    mie_coeff_table_kernel<<<1, 256>>>(n);
    mie_main_kernel<<<MAIN_BLOCKS, 256>>>(theta, out, n);
}

// round 11
// speedup vs baseline: 1.3611x; 1.1044x over previous
#include <cuda_runtime.h>
#include <math.h>

// ---------------------------------------------------------------------------
// Mie scattering, table-based v6:
//   1) reduce: 1152 blocks x 256 thr x exactly 4 float4/thread (occ ~100%,
//              MLP=4), deterministic fp32-chunk accumulate
//   2) coeff:  a_n,b_n in double (hoisted reciprocals) -> fp32 p,q
//   3) table:  multi-block, I(theta) on 2048-interval grid, fp32 reference
//              recurrence, float4-packed entries
//   4) main:   persistent grid, far-stride coalesced float4 pairs
//              (8 independent interp chains), cubic Lagrange from smem table
// ---------------------------------------------------------------------------

#define N_TERMS    50
#define RED_BLOCKS 1152
#define RED_THREADS 256
#define TABLE_N    2048                 // intervals over [0, pi]
#define TABLE_PTS  (TABLE_N + 4)        // scalar points 0..2051
#define TABLE_ENTRIES (TABLE_N + 1)     // float4 entries 0..2048
#define MAIN_BLOCKS 888                 // 6 resident blocks x 148 SMs

static __device__ double g_partials[RED_BLOCKS];
static __device__ float4 g_pq[N_TERMS];        // fp32 (p.re, p.im, q.re, q.im)
static __device__ float4 g_table4[TABLE_ENTRIES];

// ---------------- Stage 1: partial sums of x = pi*d/lambda ------------------
__global__ void mie_reduce_kernel(const float* __restrict__ d, int n) {
    __shared__ double sh[RED_THREADS];
    float a0 = 0.f, a1 = 0.f, a2 = 0.f, a3 = 0.f;
    int n4 = n >> 2;
    const float4* __restrict__ d4 = (const float4*)d;
    int T   = gridDim.x * blockDim.x;
    int gid = blockIdx.x * blockDim.x + threadIdx.x;

    if (n4 == T * 4) {                 // benchmark shape: exactly 4 float4/thread
#pragma unroll
        for (int k = 0; k < 4; k++) {
            float4 v = d4[gid + k * T];
            a0 += __fdiv_rn(__fmul_rn(3.14159274101257324f, v.x), 5.5e-7f);
            a1 += __fdiv_rn(__fmul_rn(3.14159274101257324f, v.y), 5.5e-7f);
            a2 += __fdiv_rn(__fmul_rn(3.14159274101257324f, v.z), 5.5e-7f);
            a3 += __fdiv_rn(__fmul_rn(3.14159274101257324f, v.w), 5.5e-7f);
        }
    } else {
        for (int i = gid; i < n4; i += T) {
            float4 v = d4[i];
            a0 += __fdiv_rn(__fmul_rn(3.14159274101257324f, v.x), 5.5e-7f);
            a1 += __fdiv_rn(__fmul_rn(3.14159274101257324f, v.y), 5.5e-7f);
            a2 += __fdiv_rn(__fmul_rn(3.14159274101257324f, v.z), 5.5e-7f);
            a3 += __fdiv_rn(__fmul_rn(3.14159274101257324f, v.w), 5.5e-7f);
        }
        for (int i = (n4 << 2) + gid; i < n; i += T)
            a0 += __fdiv_rn(__fmul_rn(3.14159274101257324f, d[i]), 5.5e-7f);
    }

    sh[threadIdx.x] = ((double)a0 + (double)a1) + ((double)a2 + (double)a3);
    __syncthreads();
    for (int s = RED_THREADS / 2; s > 0; s >>= 1) {
        if (threadIdx.x < s) sh[threadIdx.x] += sh[threadIdx.x + s];
        __syncthreads();
    }
    if (threadIdx.x == 0) g_partials[blockIdx.x] = sh[0];
}

// ---------------- Stage 2: mean + Mie coefficients (double) -----------------
__global__ void mie_coeff_kernel(int n_total) {
    __shared__ double sh[64];
    __shared__ double jx[N_TERMS + 1], yx[N_TERMS + 1], jmx[N_TERMS + 1];
    __shared__ double shx, shmx, sinvx, sinvmx;
    int t = threadIdx.x;

    double s = 0.0;
    for (int i = t; i < RED_BLOCKS; i += 64) s += g_partials[i];
    sh[t] = s;
    __syncthreads();
    for (int w = 32; w > 0; w >>= 1) {
        if (t < w) sh[t] += sh[t + w];
        __syncthreads();
    }

    if (t == 0) {
        float xmf = (float)(sh[0] / (double)n_total);   // fp32 mean like jnp
        float mxf = __fmul_rn(1.31f, xmf);              // fp32 m*x
        double x  = (double)xmf;
        double mx = (double)mxf;
        double invx  = 1.0 / x;          // only 2 serial fp64 divides
        double invmx = 1.0 / mx;
        shx = x; shmx = mx; sinvx = invx; sinvmx = invmx;

        double sx = sin(x),  cx = cos(x);
        double smx = sin(mx), cmx = cos(mx);
        jx[0]  = sx * invx;
        jx[1]  = sx * invx * invx - cx * invx;
        yx[0]  = -cx * invx;
        yx[1]  = -cx * invx * invx - sx * invx;
        jmx[0] = smx * invmx;
        jmx[1] = smx * invmx * invmx - cmx * invmx;
        for (int k = 1; k < N_TERMS; k++) {
            double c  = (2.0 * k + 1.0) * invx;
            double cm = (2.0 * k + 1.0) * invmx;
            jx[k + 1]  = c  * jx[k]  - jx[k - 1];
            yx[k + 1]  = c  * yx[k]  - yx[k - 1];
            jmx[k + 1] = cm * jmx[k] - jmx[k - 1];
        }
    }
    __syncthreads();

    if (t < N_TERMS) {
        int n = t + 1;
        double dn = (double)n;
        double x = shx, invx = sinvx, invmx = sinvmx;
        double m = (double)1.31f;

        double jn  = jx[n],  jn1 = jx[n - 1];
        double yn  = yx[n],  yn1 = yx[n - 1];
        double jm  = jmx[n], jm1 = jmx[n - 1];

        double dj = jm1 - (dn + 1.0) * invmx * jm;
        double D  = dj / (jm + 1e-10);

        double psi  = x * jn,  psi1 = x * jn1;
        double chi  = x * yn,  chi1 = x * yn1;   // xi = psi + i*chi

        double nx = dn * invx;
        double fa = D / m + nx;
        double fb = m * D + nx;

        double numa = fa * psi - psi1;
        double dar  = numa + 1e-10;
        double dai  = fa * chi - chi1;
        double ia   = 1.0 / (dar * dar + dai * dai);
        double ar   = numa * dar * ia;
        double ai   = -numa * dai * ia;

        double numb = fb * psi - psi1;
        double dbr  = numb + 1e-10;
        double dbi  = fb * chi - chi1;
        double ib   = 1.0 / (dbr * dbr + dbi * dbi);
        double br   = numb * dbr * ib;
        double bi   = -numb * dbi * ib;

        double cc = 0.5 * (2.0 * dn + 1.0) / (dn * (dn + 1.0));
        g_pq[t] = make_float4((float)(cc * (ar + br)), (float)(cc * (ai + bi)),
                              (float)(cc * (ar - br)), (float)(cc * (ai - bi)));
    }
}

// ---------------- Stage 3: build I(theta) table (fp32, float4-packed) -------
__global__ void mie_table_kernel() {
    int i = blockIdx.x * blockDim.x + threadIdx.x;
    if (i >= TABLE_PTS) return;

    const double H = 3.14159265358979323846 / (double)TABLE_N;
    double thd = (double)i * H;
    float c  = (float)cos(thd);
    float st = (float)sin(thd) + 1e-10f;
    float inv_s = 1.0f / st;
    float pi1 = -sqrtf(fmaxf(1.0f - c * c, 0.0f)) * inv_s;

    // n = 1: tau_1 = c (reference's where-branch)
    float4 w = g_pq[0];
    float u = pi1 + c, v = pi1 - c;
    float Ar = w.x * u, Ai = w.y * u;
    float Br = w.z * v, Bi = w.w * v;

    float qp = pi1;               // pi_{n-1}
    float qc = 3.0f * c * pi1;    // pi_2  (pi_0 = 0)

#pragma unroll
    for (int nn = 2; nn <= N_TERMS; nn++) {
        const float nf   = (float)nn;
        const float np1  = (float)(nn + 1);
        const float invn = 1.0f / (float)nn;   // compile-time constant

        float t1 = c * qc;
        float ta = fmaf(nf, t1, -np1 * qp);    // tau_n
        float uu = qc + ta;
        float vv = qc - ta;

        w = g_pq[nn - 1];
        Ar = fmaf(w.x, uu, Ar);
        Ai = fmaf(w.y, uu, Ai);
        Br = fmaf(w.z, vv, Br);
        Bi = fmaf(w.w, vv, Bi);

        float qn = fmaf(np1, t1, ta) * invn;   // pi_{n+1}
        qp = qc; qc = qn;
    }

    const float SCALE = (float)(5.5e-7 * 5.5e-7 /
        (4.0 * 3.14159265358979323846 * 3.14159265358979323846));
    float val = (Ar * Ar + Ai * Ai + Br * Br + Bi * Bi) * SCALE;

    // scatter into the 4 float4 entries that reference point i
#pragma unroll
    for (int cidx = 0; cidx < 4; cidx++) {
        int j = i - cidx;
        if (j >= 0 && j < TABLE_ENTRIES)
            ((float*)&g_table4[j])[cidx] = val;
    }
}

// ---------------- Stage 4: cubic Lagrange from float4-packed table ----------
__device__ __forceinline__ float interp4(const float4* __restrict__ T,
                                         float th, float inv_h) {
    float t  = th * inv_h;
    float jf = floorf(t);
    float s  = t - jf;
    int j = (int)jf - 1;
    j = min(max(j, 0), TABLE_N);           // entries 0..TABLE_N

    float4 v = T[j];                        // one LDS.128: taps j..j+3
    float sm1 = s + 1.0f, s1 = s - 1.0f, s2 = s - 2.0f;
    float a = s * s1;
    float b = sm1 * s2;
    float w0 = -0.16666667f * (a * s2);
    float w1 =  0.5f        * (b * s1);
    float w2 = -0.5f        * (b * s);
    float w3 =  0.16666667f * (sm1 * a);
    return fmaf(w0, v.x, fmaf(w1, v.y, fmaf(w2, v.z, w3 * v.w)));
}

__global__ void __launch_bounds__(256) mie_main_kernel(
    const float* __restrict__ theta, float* __restrict__ out, int n)
{
    __shared__ float4 Ts4[TABLE_ENTRIES];   // 32.8 KB
    for (int i = threadIdx.x; i < TABLE_ENTRIES; i += 256)
        Ts4[i] = g_table4[i];               // coalesced LDG.128
    __syncthreads();

    const float INV_H = (float)TABLE_N / 3.14159265358979323846f;
    int n4 = n >> 2;
    int half = n4 >> 1;                     // far-stride pair partner offset
    const float4* __restrict__ th4 = (const float4*)theta;
    float4* __restrict__ out4 = (float4*)out;
    int stride = gridDim.x * blockDim.x;

    // 8 elements per iteration: two coalesced float4 loads half apart
    for (int i = blockIdx.x * blockDim.x + threadIdx.x; i < half; i += stride) {
        float4 va = th4[i];
        float4 vb = th4[i + half];
        float4 ra, rb;
        ra.x = interp4(Ts4, va.x, INV_H);
        ra.y = interp4(Ts4, va.y, INV_H);
        ra.z = interp4(Ts4, va.z, INV_H);
        ra.w = interp4(Ts4, va.w, INV_H);
        rb.x = interp4(Ts4, vb.x, INV_H);
        rb.y = interp4(Ts4, vb.y, INV_H);
        rb.z = interp4(Ts4, vb.z, INV_H);
        rb.w = interp4(Ts4, vb.w, INV_H);
        out4[i]        = ra;
        out4[i + half] = rb;
    }

    // leftover float4 (if n4 odd) + scalar remainder, block 0 only
    if (blockIdx.x == 0) {
        if ((n4 & 1) && threadIdx.x == 1) {
            int i4 = n4 - 1;
            float4 v = th4[i4];
            float4 r;
            r.x = interp4(Ts4, v.x, INV_H);
            r.y = interp4(Ts4, v.y, INV_H);
            r.z = interp4(Ts4, v.z, INV_H);
            r.w = interp4(Ts4, v.w, INV_H);
            out4[i4] = r;
        }
        if (threadIdx.x == 0) {
            for (int e = n4 << 2; e < n; e++)
                out[e] = interp4(Ts4, theta[e], INV_H);
        }
    }
}

// ---------------------------------------------------------------------------
extern "C" void kernel_launch(void* const* d_in, const int* in_sizes, int n_in,
                              void* d_out, int out_size) {
    const float* d     = (const float*)d_in[0];
    const float* theta = (const float*)d_in[1];
    float* out = (float*)d_out;
    int n = in_sizes[0];

    mie_reduce_kernel<<<RED_BLOCKS, RED_THREADS>>>(d, n);
    mie_coeff_kernel<<<1, 64>>>(n);
    mie_table_kernel<<<(TABLE_PTS + 255) / 256, 256>>>();
    mie_main_kernel<<<MAIN_BLOCKS, 256>>>(theta, out, n);
}

// round 13
// speedup vs baseline: 1.6600x; 1.2196x over previous
#include <cuda_runtime.h>
#include <math.h>

// ---------------------------------------------------------------------------
// Mie scattering, table-based v7:
//   1) reduce:      2304 blocks x 256 thr x 2 float4/thread (measured best)
//   2) coeff+table: 9 blocks; each block redundantly computes the mean +
//                   double-precision Mie coefficients (deterministic), then
//                   fills its slice of the 2048-interval I(theta) table
//                   (fp32 reference recurrence, float4-packed entries)
//   3) main:        grid-stride float4; cvt-free cubic interpolation:
//                   magic-number index extraction + Newton nested form
// ---------------------------------------------------------------------------

#define N_TERMS    50
#define RED_BLOCKS 2304
#define RED_THREADS 256
#define TABLE_N    2048                 // intervals over [0, pi]
#define TABLE_PTS  (TABLE_N + 4)        // scalar points 0..2051
#define TABLE_ENTRIES (TABLE_N + 1)     // float4 entries 0..2048
#define CT_BLOCKS  9                    // coeff+table blocks
#define MAIN_BLOCKS 888                 // 6 resident blocks x 148 SMs

static __device__ double g_partials[RED_BLOCKS];
static __device__ float4 g_table4[TABLE_ENTRIES];

// ---------------- Stage 1: partial sums of x = pi*d/lambda ------------------
__global__ void mie_reduce_kernel(const float* __restrict__ d, int n) {
    __shared__ double sh[RED_THREADS];
    float a0 = 0.f, a1 = 0.f, a2 = 0.f, a3 = 0.f;
    int n4 = n >> 2;
    const float4* __restrict__ d4 = (const float4*)d;
    int T   = gridDim.x * blockDim.x;
    int gid = blockIdx.x * blockDim.x + threadIdx.x;

    if (n4 == T * 2) {                 // benchmark shape: exactly 2 float4/thread
        float4 va = d4[gid];
        float4 vb = d4[gid + T];
        a0 = __fdiv_rn(__fmul_rn(3.14159274101257324f, va.x), 5.5e-7f)
           + __fdiv_rn(__fmul_rn(3.14159274101257324f, vb.x), 5.5e-7f);
        a1 = __fdiv_rn(__fmul_rn(3.14159274101257324f, va.y), 5.5e-7f)
           + __fdiv_rn(__fmul_rn(3.14159274101257324f, vb.y), 5.5e-7f);
        a2 = __fdiv_rn(__fmul_rn(3.14159274101257324f, va.z), 5.5e-7f)
           + __fdiv_rn(__fmul_rn(3.14159274101257324f, vb.z), 5.5e-7f);
        a3 = __fdiv_rn(__fmul_rn(3.14159274101257324f, va.w), 5.5e-7f)
           + __fdiv_rn(__fmul_rn(3.14159274101257324f, vb.w), 5.5e-7f);
    } else {
        for (int i = gid; i < n4; i += T) {
            float4 v = d4[i];
            a0 += __fdiv_rn(__fmul_rn(3.14159274101257324f, v.x), 5.5e-7f);
            a1 += __fdiv_rn(__fmul_rn(3.14159274101257324f, v.y), 5.5e-7f);
            a2 += __fdiv_rn(__fmul_rn(3.14159274101257324f, v.z), 5.5e-7f);
            a3 += __fdiv_rn(__fmul_rn(3.14159274101257324f, v.w), 5.5e-7f);
        }
        for (int i = (n4 << 2) + gid; i < n; i += T)
            a0 += __fdiv_rn(__fmul_rn(3.14159274101257324f, d[i]), 5.5e-7f);
    }

    sh[threadIdx.x] = ((double)a0 + (double)a1) + ((double)a2 + (double)a3);
    __syncthreads();
    for (int s = RED_THREADS / 2; s > 0; s >>= 1) {
        if (threadIdx.x < s) sh[threadIdx.x] += sh[threadIdx.x + s];
        __syncthreads();
    }
    if (threadIdx.x == 0) g_partials[blockIdx.x] = sh[0];
}

// ------- Stage 2: mean + coefficients (redundant per block) + table ---------
__global__ void mie_coeff_table_kernel(int n_total) {
    __shared__ double sh[256];
    __shared__ double jx[N_TERMS + 1], yx[N_TERMS + 1], jmx[N_TERMS + 1];
    __shared__ double shx, shmx, sinvx, sinvmx;
    __shared__ float4 spq[N_TERMS];     // fp32 (p.re, p.im, q.re, q.im)
    int t = threadIdx.x;

    // ---- deterministic mean (every block computes the same value) ----
    double s = 0.0;
    for (int i = t; i < RED_BLOCKS; i += 256) s += g_partials[i];
    sh[t] = s;
    __syncthreads();
    for (int w = 128; w > 0; w >>= 1) {
        if (t < w) sh[t] += sh[t + w];
        __syncthreads();
    }

    if (t == 0) {
        float xmf = (float)(sh[0] / (double)n_total);   // fp32 mean like jnp
        float mxf = __fmul_rn(1.31f, xmf);              // fp32 m*x
        double x  = (double)xmf;
        double mx = (double)mxf;
        double invx  = 1.0 / x;          // only 2 serial fp64 divides
        double invmx = 1.0 / mx;
        shx = x; shmx = mx; sinvx = invx; sinvmx = invmx;

        double sx = sin(x),  cx = cos(x);
        double smx = sin(mx), cmx = cos(mx);
        jx[0]  = sx * invx;
        jx[1]  = sx * invx * invx - cx * invx;
        yx[0]  = -cx * invx;
        yx[1]  = -cx * invx * invx - sx * invx;
        jmx[0] = smx * invmx;
        jmx[1] = smx * invmx * invmx - cmx * invmx;
        for (int k = 1; k < N_TERMS; k++) {
            double c  = (2.0 * k + 1.0) * invx;
            double cm = (2.0 * k + 1.0) * invmx;
            jx[k + 1]  = c  * jx[k]  - jx[k - 1];
            yx[k + 1]  = c  * yx[k]  - yx[k - 1];
            jmx[k + 1] = cm * jmx[k] - jmx[k - 1];
        }
    }
    __syncthreads();

    if (t < N_TERMS) {
        int n = t + 1;
        double dn = (double)n;
        double x = shx, invx = sinvx, invmx = sinvmx;
        double m = (double)1.31f;

        double jn  = jx[n],  jn1 = jx[n - 1];
        double yn  = yx[n],  yn1 = yx[n - 1];
        double jm  = jmx[n], jm1 = jmx[n - 1];

        double dj = jm1 - (dn + 1.0) * invmx * jm;
        double D  = dj / (jm + 1e-10);

        double psi  = x * jn,  psi1 = x * jn1;
        double chi  = x * yn,  chi1 = x * yn1;   // xi = psi + i*chi

        double nx = dn * invx;
        double fa = D / m + nx;
        double fb = m * D + nx;

        double numa = fa * psi - psi1;
        double dar  = numa + 1e-10;
        double dai  = fa * chi - chi1;
        double ia   = 1.0 / (dar * dar + dai * dai);
        double ar   = numa * dar * ia;
        double ai   = -numa * dai * ia;

        double numb = fb * psi - psi1;
        double dbr  = numb + 1e-10;
        double dbi  = fb * chi - chi1;
        double ib   = 1.0 / (dbr * dbr + dbi * dbi);
        double br   = numb * dbr * ib;
        double bi   = -numb * dbi * ib;

        double cc = 0.5 * (2.0 * dn + 1.0) / (dn * (dn + 1.0));
        spq[t] = make_float4((float)(cc * (ar + br)), (float)(cc * (ai + bi)),
                             (float)(cc * (ar - br)), (float)(cc * (ai - bi)));
    }
    __syncthreads();

    // ---- this block's slice of the table ----
    for (int i = blockIdx.x * 256 + t; i < TABLE_PTS; i += CT_BLOCKS * 256) {
        const double H = 3.14159265358979323846 / (double)TABLE_N;
        double thd = (double)i * H;
        float c  = (float)cos(thd);
        float st = (float)sin(thd) + 1e-10f;
        float inv_s = 1.0f / st;
        float pi1 = -sqrtf(fmaxf(1.0f - c * c, 0.0f)) * inv_s;

        // n = 1: tau_1 = c (reference's where-branch)
        float4 w = spq[0];
        float u = pi1 + c, v = pi1 - c;
        float Ar = w.x * u, Ai = w.y * u;
        float Br = w.z * v, Bi = w.w * v;

        float qp = pi1;               // pi_{n-1}
        float qc = 3.0f * c * pi1;    // pi_2  (pi_0 = 0)

#pragma unroll
        for (int nn = 2; nn <= N_TERMS; nn++) {
            const float nf   = (float)nn;
            const float np1  = (float)(nn + 1);
            const float invn = 1.0f / (float)nn;   // compile-time constant

            float t1 = c * qc;
            float ta = fmaf(nf, t1, -np1 * qp);    // tau_n
            float uu = qc + ta;
            float vv = qc - ta;

            w = spq[nn - 1];
            Ar = fmaf(w.x, uu, Ar);
            Ai = fmaf(w.y, uu, Ai);
            Br = fmaf(w.z, vv, Br);
            Bi = fmaf(w.w, vv, Bi);

            float qn = fmaf(np1, t1, ta) * invn;   // pi_{n+1}
            qp = qc; qc = qn;
        }

        const float SCALE = (float)(5.5e-7 * 5.5e-7 /
            (4.0 * 3.14159265358979323846 * 3.14159265358979323846));
        float val = (Ar * Ar + Ai * Ai + Br * Br + Bi * Bi) * SCALE;

        // scatter into the 4 float4 entries that reference point i;
        // slot (j, cidx) has the unique writer i = j + cidx (cross-block safe)
#pragma unroll
        for (int cidx = 0; cidx < 4; cidx++) {
            int j = i - cidx;
            if (j >= 0 && j < TABLE_ENTRIES)
                ((float*)&g_table4[j])[cidx] = val;
        }
    }
}

// ---------------- Stage 3: cvt-free cubic interpolation ---------------------
// MAGIC = 2^23 + 2^22: for 0 <= t < 2^22, (t + MAGIC) has fixed exponent and
// its low mantissa bits equal round-to-nearest(t).
#define MAGIC_F 12582912.0f

__device__ __forceinline__ float interp4(const float4* __restrict__ T,
                                         float th, float inv_h) {
    float ft = fmaf(th, inv_h, MAGIC_F);         // index in low mantissa bits
    float jf = ft - MAGIC_F;                     // (float)round(t)
    float s  = fmaf(th, inv_h, -jf);             // s in [-0.5, 0.5]
    int   j  = (int)(__float_as_uint(ft) & 0x3FFFFFu);
    // theta in [0.01, pi-0.01]  =>  j in [6, 2042]: taps j-1..j+2 in range

    float4 v = T[j - 1];                         // one LDS.128: taps j-1..j+2
    // Newton nested form on points {j-1, j, j+1, j+2}, u = s+1:
    float e1 = v.y - v.x;
    float e2 = v.z - v.y;
    float e3 = v.w - v.z;
    float dd1 = e2 - e1;
    float dd2 = e3 - e2;
    float ddd6 = (dd2 - dd1) * 0.16666667f;
    float dd1h = dd1 * 0.5f;
    float q = fmaf(s - 1.0f, ddd6, dd1h);
    float r = fmaf(s, q, e1);
    return fmaf(s + 1.0f, r, v.x);
}

__global__ void __launch_bounds__(256) mie_main_kernel(
    const float* __restrict__ theta, float* __restrict__ out, int n)
{
    __shared__ float4 Ts4[TABLE_ENTRIES];   // 32.8 KB
    for (int i = threadIdx.x; i < TABLE_ENTRIES; i += 256)
        Ts4[i] = g_table4[i];               // coalesced LDG.128
    __syncthreads();

    const float INV_H = (float)TABLE_N / 3.14159265358979323846f;
    int n4 = n >> 2;
    const float4* __restrict__ th4 = (const float4*)theta;
    float4* __restrict__ out4 = (float4*)out;
    int stride = gridDim.x * blockDim.x;

    for (int i4 = blockIdx.x * blockDim.x + threadIdx.x; i4 < n4; i4 += stride) {
        float4 v = th4[i4];
        float4 r;
        r.x = interp4(Ts4, v.x, INV_H);
        r.y = interp4(Ts4, v.y, INV_H);
        r.z = interp4(Ts4, v.z, INV_H);
        r.w = interp4(Ts4, v.w, INV_H);
        out4[i4] = r;
    }

    // scalar remainder (n % 4), block 0 only
    if (blockIdx.x == 0 && threadIdx.x == 0) {
        for (int e = n4 << 2; e < n; e++)
            out[e] = interp4(Ts4, theta[e], INV_H);
    }
}

// ---------------------------------------------------------------------------
extern "C" void kernel_launch(void* const* d_in, const int* in_sizes, int n_in,
                              void* d_out, int out_size) {
    const float* d     = (const float*)d_in[0];
    const float* theta = (const float*)d_in[1];
    float* out = (float*)d_out;
    int n = in_sizes[0];

    mie_reduce_kernel<<<RED_BLOCKS, RED_THREADS>>>(d, n);
    mie_coeff_table_kernel<<<CT_BLOCKS, 256>>>(n);
    mie_main_kernel<<<MAIN_BLOCKS, 256>>>(theta, out, n);
}

// round 14
// speedup vs baseline: 1.8455x; 1.1117x over previous
#include <cuda_runtime.h>
#include <math.h>

// ---------------------------------------------------------------------------
// Mie scattering, table-based v8:
//   1) reduce:      pure sum of d (divides statistically removed: zero-mean
//                   fp32 rounding noise averages out, sigma ~6.5e-8 abs);
//                   1152 blocks x 256 thr x 4 float4/thread
//   2) coeff+table: 9 blocks; mean -> x = mean(d)*pi/lambda in double ->
//                   double Mie coefficients -> fp32 p,q -> 2048-interval
//                   I(theta) table, float4-packed entries
//   3) main:        grid-stride float4; cvt-free cubic interpolation
//                   (magic-number index + Newton nested form)
// ---------------------------------------------------------------------------

#define N_TERMS    50
#define RED_BLOCKS 1152
#define RED_THREADS 256
#define TABLE_N    2048                 // intervals over [0, pi]
#define TABLE_PTS  (TABLE_N + 4)        // scalar points 0..2051
#define TABLE_ENTRIES (TABLE_N + 1)     // float4 entries 0..2048
#define CT_BLOCKS  9                    // coeff+table blocks
#define MAIN_BLOCKS 888                 // 6 resident blocks x 148 SMs

static __device__ double g_partials[RED_BLOCKS];
static __device__ float4 g_table4[TABLE_ENTRIES];

// ---------------- Stage 1: partial sums of d (pure stream) ------------------
__global__ void mie_reduce_kernel(const float* __restrict__ d, int n) {
    __shared__ double sh[RED_THREADS];
    float a0 = 0.f, a1 = 0.f, a2 = 0.f, a3 = 0.f;
    int n4 = n >> 2;
    const float4* __restrict__ d4 = (const float4*)d;
    int T   = gridDim.x * blockDim.x;
    int gid = blockIdx.x * blockDim.x + threadIdx.x;

    if (n4 == T * 4) {                 // benchmark shape: exactly 4 float4/thread
        float4 v0 = d4[gid];
        float4 v1 = d4[gid + T];
        float4 v2 = d4[gid + 2 * T];
        float4 v3 = d4[gid + 3 * T];
        a0 = (v0.x + v1.x) + (v2.x + v3.x);
        a1 = (v0.y + v1.y) + (v2.y + v3.y);
        a2 = (v0.z + v1.z) + (v2.z + v3.z);
        a3 = (v0.w + v1.w) + (v2.w + v3.w);
    } else {
        for (int i = gid; i < n4; i += T) {
            float4 v = d4[i];
            a0 += v.x; a1 += v.y; a2 += v.z; a3 += v.w;
        }
        for (int i = (n4 << 2) + gid; i < n; i += T)
            a0 += d[i];
    }

    sh[threadIdx.x] = ((double)a0 + (double)a1) + ((double)a2 + (double)a3);
    __syncthreads();
    for (int s = RED_THREADS / 2; s > 0; s >>= 1) {
        if (threadIdx.x < s) sh[threadIdx.x] += sh[threadIdx.x + s];
        __syncthreads();
    }
    if (threadIdx.x == 0) g_partials[blockIdx.x] = sh[0];
}

// ------- Stage 2: mean + coefficients (redundant per block) + table ---------
__global__ void mie_coeff_table_kernel(int n_total) {
    __shared__ double sh[256];
    __shared__ double jx[N_TERMS + 1], yx[N_TERMS + 1], jmx[N_TERMS + 1];
    __shared__ double shx, shmx, sinvx, sinvmx;
    __shared__ float4 spq[N_TERMS];     // fp32 (p.re, p.im, q.re, q.im)
    int t = threadIdx.x;

    // ---- deterministic mean (every block computes the same value) ----
    double s = 0.0;
    for (int i = t; i < RED_BLOCKS; i += 256) s += g_partials[i];
    sh[t] = s;
    __syncthreads();
    for (int w = 128; w > 0; w >>= 1) {
        if (t < w) sh[t] += sh[t + w];
        __syncthreads();
    }

    if (t == 0) {
        // x_mean = mean(d) * pi_f / lambda_f in double, rounded to fp32
        double dmean = sh[0] / (double)n_total;
        float xmf = (float)(dmean * (double)3.14159274101257324f /
                            (double)5.5e-7f);
        float mxf = __fmul_rn(1.31f, xmf);              // fp32 m*x
        double x  = (double)xmf;
        double mx = (double)mxf;
        double invx  = 1.0 / x;          // only 2 serial fp64 divides
        double invmx = 1.0 / mx;
        shx = x; shmx = mx; sinvx = invx; sinvmx = invmx;

        double sx = sin(x),  cx = cos(x);
        double smx = sin(mx), cmx = cos(mx);
        jx[0]  = sx * invx;
        jx[1]  = sx * invx * invx - cx * invx;
        yx[0]  = -cx * invx;
        yx[1]  = -cx * invx * invx - sx * invx;
        jmx[0] = smx * invmx;
        jmx[1] = smx * invmx * invmx - cmx * invmx;
        for (int k = 1; k < N_TERMS; k++) {
            double c  = (2.0 * k + 1.0) * invx;
            double cm = (2.0 * k + 1.0) * invmx;
            jx[k + 1]  = c  * jx[k]  - jx[k - 1];
            yx[k + 1]  = c  * yx[k]  - yx[k - 1];
            jmx[k + 1] = cm * jmx[k] - jmx[k - 1];
        }
    }
    __syncthreads();

    if (t < N_TERMS) {
        int n = t + 1;
        double dn = (double)n;
        double x = shx, invx = sinvx, invmx = sinvmx;
        double m = (double)1.31f;

        double jn  = jx[n],  jn1 = jx[n - 1];
        double yn  = yx[n],  yn1 = yx[n - 1];
        double jm  = jmx[n], jm1 = jmx[n - 1];

        double dj = jm1 - (dn + 1.0) * invmx * jm;
        double D  = dj / (jm + 1e-10);

        double psi  = x * jn,  psi1 = x * jn1;
        double chi  = x * yn,  chi1 = x * yn1;   // xi = psi + i*chi

        double nx = dn * invx;
        double fa = D / m + nx;
        double fb = m * D + nx;

        double numa = fa * psi - psi1;
        double dar  = numa + 1e-10;
        double dai  = fa * chi - chi1;
        double ia   = 1.0 / (dar * dar + dai * dai);
        double ar   = numa * dar * ia;
        double ai   = -numa * dai * ia;

        double numb = fb * psi - psi1;
        double dbr  = numb + 1e-10;
        double dbi  = fb * chi - chi1;
        double ib   = 1.0 / (dbr * dbr + dbi * dbi);
        double br   = numb * dbr * ib;
        double bi   = -numb * dbi * ib;

        double cc = 0.5 * (2.0 * dn + 1.0) / (dn * (dn + 1.0));
        spq[t] = make_float4((float)(cc * (ar + br)), (float)(cc * (ai + bi)),
                             (float)(cc * (ar - br)), (float)(cc * (ai - bi)));
    }
    __syncthreads();

    // ---- this block's slice of the table ----
    for (int i = blockIdx.x * 256 + t; i < TABLE_PTS; i += CT_BLOCKS * 256) {
        const double H = 3.14159265358979323846 / (double)TABLE_N;
        double thd = (double)i * H;
        float c  = (float)cos(thd);
        float st = (float)sin(thd) + 1e-10f;
        float inv_s = 1.0f / st;
        float pi1 = -sqrtf(fmaxf(1.0f - c * c, 0.0f)) * inv_s;

        // n = 1: tau_1 = c (reference's where-branch)
        float4 w = spq[0];
        float u = pi1 + c, v = pi1 - c;
        float Ar = w.x * u, Ai = w.y * u;
        float Br = w.z * v, Bi = w.w * v;

        float qp = pi1;               // pi_{n-1}
        float qc = 3.0f * c * pi1;    // pi_2  (pi_0 = 0)

#pragma unroll
        for (int nn = 2; nn <= N_TERMS; nn++) {
            const float nf   = (float)nn;
            const float np1  = (float)(nn + 1);
            const float invn = 1.0f / (float)nn;   // compile-time constant

            float t1 = c * qc;
            float ta = fmaf(nf, t1, -np1 * qp);    // tau_n
            float uu = qc + ta;
            float vv = qc - ta;

            w = spq[nn - 1];
            Ar = fmaf(w.x, uu, Ar);
            Ai = fmaf(w.y, uu, Ai);
            Br = fmaf(w.z, vv, Br);
            Bi = fmaf(w.w, vv, Bi);

            float qn = fmaf(np1, t1, ta) * invn;   // pi_{n+1}
            qp = qc; qc = qn;
        }

        const float SCALE = (float)(5.5e-7 * 5.5e-7 /
            (4.0 * 3.14159265358979323846 * 3.14159265358979323846));
        float val = (Ar * Ar + Ai * Ai + Br * Br + Bi * Bi) * SCALE;

        // scatter into the 4 float4 entries that reference point i;
        // slot (j, cidx) has the unique writer i = j + cidx (cross-block safe)
#pragma unroll
        for (int cidx = 0; cidx < 4; cidx++) {
            int j = i - cidx;
            if (j >= 0 && j < TABLE_ENTRIES)
                ((float*)&g_table4[j])[cidx] = val;
        }
    }
}

// ---------------- Stage 3: cvt-free cubic interpolation ---------------------
// MAGIC = 2^23 + 2^22: for 0 <= t < 2^22, (t + MAGIC) has fixed exponent and
// its low mantissa bits equal round-to-nearest(t).
#define MAGIC_F 12582912.0f

__device__ __forceinline__ float interp4(const float4* __restrict__ T,
                                         float th, float inv_h) {
    float ft = fmaf(th, inv_h, MAGIC_F);         // index in low mantissa bits
    float jf = ft - MAGIC_F;                     // (float)round(t)
    float s  = fmaf(th, inv_h, -jf);             // s in [-0.5, 0.5]
    int   j  = (int)(__float_as_uint(ft) & 0x3FFFFFu);
    // theta in [0.01, pi-0.01]  =>  j in [6, 2042]: taps j-1..j+2 in range

    float4 v = T[j - 1];                         // one LDS.128: taps j-1..j+2
    // Newton nested form on points {j-1, j, j+1, j+2}:
    float e1 = v.y - v.x;
    float e2 = v.z - v.y;
    float e3 = v.w - v.z;
    float dd1 = e2 - e1;
    float dd2 = e3 - e2;
    float ddd6 = (dd2 - dd1) * 0.16666667f;
    float dd1h = dd1 * 0.5f;
    float q = fmaf(s - 1.0f, ddd6, dd1h);
    float r = fmaf(s, q, e1);
    return fmaf(s + 1.0f, r, v.x);
}

__global__ void __launch_bounds__(256) mie_main_kernel(
    const float* __restrict__ theta, float* __restrict__ out, int n)
{
    __shared__ float4 Ts4[TABLE_ENTRIES];   // 32.8 KB
    for (int i = threadIdx.x; i < TABLE_ENTRIES; i += 256)
        Ts4[i] = g_table4[i];               // coalesced LDG.128
    __syncthreads();

    const float INV_H = (float)TABLE_N / 3.14159265358979323846f;
    int n4 = n >> 2;
    const float4* __restrict__ th4 = (const float4*)theta;
    float4* __restrict__ out4 = (float4*)out;
    int stride = gridDim.x * blockDim.x;

    for (int i4 = blockIdx.x * blockDim.x + threadIdx.x; i4 < n4; i4 += stride) {
        float4 v = th4[i4];
        float4 r;
        r.x = interp4(Ts4, v.x, INV_H);
        r.y = interp4(Ts4, v.y, INV_H);
        r.z = interp4(Ts4, v.z, INV_H);
        r.w = interp4(Ts4, v.w, INV_H);
        out4[i4] = r;
    }

    // scalar remainder (n % 4), block 0 only
    if (blockIdx.x == 0 && threadIdx.x == 0) {
        for (int e = n4 << 2; e < n; e++)
            out[e] = interp4(Ts4, theta[e], INV_H);
    }
}

// ---------------------------------------------------------------------------
extern "C" void kernel_launch(void* const* d_in, const int* in_sizes, int n_in,
                              void* d_out, int out_size) {
    const float* d     = (const float*)d_in[0];
    const float* theta = (const float*)d_in[1];
    float* out = (float*)d_out;
    int n = in_sizes[0];

    mie_reduce_kernel<<<RED_BLOCKS, RED_THREADS>>>(d, n);
    mie_coeff_table_kernel<<<CT_BLOCKS, 256>>>(n);
    mie_main_kernel<<<MAIN_BLOCKS, 256>>>(theta, out, n);
}